// round 15
// baseline (speedup 1.0000x reference)
#include <cuda_runtime.h>
#include <cuda_fp16.h>
#include <mma.h>
#include <cstdint>

using namespace nvcuda;

// ---------------- problem constants ----------------
constexpr int NN = 50000;
constexpr int NE = 800000;
constexpr int IND = 64;
constexpr int HD = 128;
constexpr int NG = 1024;
constexpr float SLOPE = 0.01f;

constexpr int TM  = 48;    // rows per tile
constexpr int LDH = 136;   // half smem leading dim
constexpr int LDF = 132;   // float smem leading dim
constexpr int NT  = 384;   // threads per block
constexpr int NTILES = (NN + TM - 1) / TM;   // 1042

// ---------------- scratch (device globals) ----------------
__device__ __align__(256) __half g_h0[(size_t)NN * HD];
__device__ __align__(256) __half g_h1[(size_t)NN * HD];
__device__ __align__(256) __half g_wh[131072];
__device__ __align__(256) float g_sums[(size_t)NG * HD];
__device__ __align__(256) int   g_batch[NN];
__device__ __align__(256) int   g_deg[NN];
__device__ __align__(256) int   g_cur[NN];
__device__ __align__(256) int   g_rowstart[NN + 1];
__device__ __align__(256) int   g_csr[NE];
__device__ int g_is64;

// weight offsets in g_wh (halves)
constexpr int OW_RES = 0;
constexpr int OW_W10 = 8192;
constexpr int OW_W20 = 16384;
constexpr int OW_WS1 = 32768;
constexpr int OW_WS2 = 81920;

#define NBAR_SYNC(id, cnt)   asm volatile("bar.sync %0, %1;"   :: "r"(id), "r"(cnt) : "memory")
#define NBAR_ARRIVE(id, cnt) asm volatile("bar.arrive %0, %1;" :: "r"(id), "r"(cnt) : "memory")

// ============================================================
// setup kernels (unchanged from R14)
// ============================================================
__global__ void zero_detect(const int* __restrict__ rawE) {
    int i = blockIdx.x * blockDim.x + threadIdx.x;
    if (i < NN) { g_deg[i] = 0; g_cur[i] = 0; }
    if (i < NG * HD) g_sums[i] = 0.f;
    if (blockIdx.x == 0) {
        __shared__ int s_any;
        if (threadIdx.x == 0) s_any = 0;
        __syncthreads();
        int bad = 0;
        for (int k = threadIdx.x; k < 4096; k += blockDim.x) bad |= rawE[2 * k + 1];
        if (bad) atomicOr(&s_any, 1);
        __syncthreads();
        if (threadIdx.x == 0) g_is64 = (s_any == 0) ? 1 : 0;
    }
}
__global__ void hist_conv(const void* __restrict__ rawE, const void* __restrict__ rawB) {
    int i = blockIdx.x * blockDim.x + threadIdx.x;
    int is64 = g_is64;
    if (i < NE) {
        int d = is64 ? (int)((const long long*)rawE)[NE + i] : ((const int*)rawE)[NE + i];
        atomicAdd(&g_deg[d], 1);
    }
    if (i < NN) {
        g_batch[i] = is64 ? (int)((const long long*)rawB)[i] : ((const int*)rawB)[i];
    }
}
__global__ void __launch_bounds__(1024) scan_deg() {
    __shared__ int part[1024];
    int tid = threadIdx.x;
    const int CH = (NN + 1023) / 1024;
    int base = tid * CH;
    int s = 0;
    for (int i = 0; i < CH; i++) {
        int idx = base + i;
        if (idx < NN) s += g_deg[idx];
    }
    part[tid] = s;
    __syncthreads();
    for (int off = 1; off < 1024; off <<= 1) {
        int v = (tid >= off) ? part[tid - off] : 0;
        __syncthreads();
        part[tid] += v;
        __syncthreads();
    }
    int run = (tid > 0) ? part[tid - 1] : 0;
    for (int i = 0; i < CH; i++) {
        int idx = base + i;
        if (idx < NN) {
            g_rowstart[idx] = run;
            run += g_deg[idx];
        }
    }
    if (tid == 1023) g_rowstart[NN] = run;
}
__global__ void fill_csr_convw(const void* __restrict__ rawE,
                               const float* __restrict__ l0_W1, const float* __restrict__ l0_W2,
                               const float* __restrict__ l0_Wres,
                               const float* __restrict__ Ws1, const float* __restrict__ Ws2) {
    int e = blockIdx.x * blockDim.x + threadIdx.x;
    if (e < 131072) {
        float v;
        if (e < 8192)        v = __ldg(&l0_Wres[e]);
        else if (e < 16384)  v = __ldg(&l0_W1[e - 8192]);
        else if (e < 32768)  v = __ldg(&l0_W2[e - 16384]);
        else if (e < 81920)  v = __ldg(&Ws1[e - 32768]);
        else                 v = __ldg(&Ws2[e - 81920]);
        g_wh[e] = __float2half_rn(v);
    }
    if (e >= NE) return;
    int is64 = g_is64;
    int s = is64 ? (int)((const long long*)rawE)[e]      : ((const int*)rawE)[e];
    int d = is64 ? (int)((const long long*)rawE)[NE + e] : ((const int*)rawE)[NE + e];
    int p = atomicAdd(&g_cur[d], 1);
    g_csr[g_rowstart[d] + p] = s;
}

// ============================================================
// L0 kernel: R14's fused layer (gather fp32 64-dim + MLP + reg residual)
// ============================================================
__global__ void __launch_bounds__(NT, 4)
gin_l0(const float* __restrict__ Xf,
       const __half* __restrict__ W1, const float* __restrict__ b1,
       const __half* __restrict__ W2, const float* __restrict__ b2,
       const __half* __restrict__ Wres,
       __half* __restrict__ Out) {
    extern __shared__ char smc[];
    __half* sAh = (__half*)smc;
    __half* sWh = (__half*)(smc + 13056);
    float*  sD  = (float*)(smc + 13056);

    int tid = threadIdx.x;
    int wid = tid >> 5;
    int r0 = blockIdx.x * TM;
    int wrow = wid % 3;
    int ncg  = wid / 3;

    wmma::fragment<wmma::accumulator, 16, 16, 16, float> acc[2];

    auto loadW = [&](const __half* __restrict__ src, int K) {
        int n = K * 16;
        for (int idx = tid; idx < n; idx += NT) {
            int row = idx >> 4, c = idx & 15;
            uint4 v = __ldg((const uint4*)src + (size_t)row * 16 + c);
            *(uint4*)(sWh + row * LDH + c * 8) = v;
        }
    };
    auto mmaAccum = [&](int ksteps) {
        for (int k = 0; k < ksteps; k++) {
            wmma::fragment<wmma::matrix_a, 16, 16, 16, __half, wmma::row_major> af;
            wmma::load_matrix_sync(af, sAh + wrow * 16 * LDH + k * 16, LDH);
#pragma unroll
            for (int n = 0; n < 2; n++) {
                wmma::fragment<wmma::matrix_b, 16, 16, 16, __half, wmma::row_major> bf;
                wmma::load_matrix_sync(bf, sWh + k * 16 * LDH + ncg * 32 + n * 16, LDH);
                wmma::mma_sync(acc[n], af, bf, acc[n]);
            }
        }
    };
    auto storeAcc = [&]() {
#pragma unroll
        for (int n = 0; n < 2; n++)
            wmma::store_matrix_sync(sD + wrow * 16 * LDF + ncg * 32 + n * 16, acc[n], LDF, wmma::mem_row_major);
    };

    // gather (fp32 64-dim, 2 rows per half-warp)
    {
        int hw = tid >> 4;
        int t = tid & 15;
#pragma unroll
        for (int rr = 0; rr < 2; rr++) {
            int row = hw * 2 + rr;
            int node = r0 + row;
            float4 a = make_float4(0.f, 0.f, 0.f, 0.f);
            if (node < NN) {
                a = __ldg((const float4*)(Xf + (size_t)node * 64) + t);
                int beg = __ldg(&g_rowstart[node]);
                int end = __ldg(&g_rowstart[node + 1]);
                int i = beg;
                for (; i + 4 <= end; i += 4) {
                    int s0 = __ldg(&g_csr[i + 0]);
                    int s1 = __ldg(&g_csr[i + 1]);
                    int s2 = __ldg(&g_csr[i + 2]);
                    int s3 = __ldg(&g_csr[i + 3]);
                    float4 v0 = __ldg((const float4*)(Xf + (size_t)s0 * 64) + t);
                    float4 v1 = __ldg((const float4*)(Xf + (size_t)s1 * 64) + t);
                    float4 v2 = __ldg((const float4*)(Xf + (size_t)s2 * 64) + t);
                    float4 v3 = __ldg((const float4*)(Xf + (size_t)s3 * 64) + t);
                    a.x += (v0.x + v1.x) + (v2.x + v3.x);
                    a.y += (v0.y + v1.y) + (v2.y + v3.y);
                    a.z += (v0.z + v1.z) + (v2.z + v3.z);
                    a.w += (v0.w + v1.w) + (v2.w + v3.w);
                }
                for (; i < end; i++) {
                    int s = __ldg(&g_csr[i]);
                    float4 v = __ldg((const float4*)(Xf + (size_t)s * 64) + t);
                    a.x += v.x; a.y += v.y; a.z += v.z; a.w += v.w;
                }
            }
            __half2* o = (__half2*)(sAh + row * LDH + t * 4);
            o[0] = __floats2half2_rn(a.x, a.y);
            o[1] = __floats2half2_rn(a.z, a.w);
        }
    }
    loadW(W1, 64);
    __syncthreads();

    // phase 1
#pragma unroll
    for (int n = 0; n < 2; n++) wmma::fill_fragment(acc[n], 0.f);
    mmaAccum(4);
    __syncthreads();
    storeAcc();
    __syncthreads();
    for (int idx = tid; idx < TM * 128; idx += NT) {
        int row = idx >> 7, col = idx & 127;
        float v = fmaxf(sD[row * LDF + col] + __ldg(&b1[col]), 0.f);
        sAh[row * LDH + col] = __float2half_rn(v);
    }
    __syncthreads();
    loadW(W2, 128);
    __syncthreads();

    // phase 2
#pragma unroll
    for (int n = 0; n < 2; n++) wmma::fill_fragment(acc[n], 0.f);
    mmaAccum(8);

    // residual: acc += x @ Wres
    __syncthreads();
    for (int idx = tid; idx < TM * 16; idx += NT) {
        int row = idx >> 4, c4 = idx & 15;
        float4 v = make_float4(0.f, 0.f, 0.f, 0.f);
        if (r0 + row < NN) v = __ldg((const float4*)(Xf + (size_t)(r0 + row) * 64) + c4);
        __half2* o = (__half2*)(sAh + row * LDH + c4 * 4);
        o[0] = __floats2half2_rn(v.x, v.y);
        o[1] = __floats2half2_rn(v.z, v.w);
    }
    loadW(Wres, 64);
    __syncthreads();
    mmaAccum(4);
    __syncthreads();
    storeAcc();
    __syncthreads();

    // epilogue
    for (int idx = tid; idx < TM * 32; idx += NT) {
        int row = idx >> 5, c4 = idx & 31;
        int node = r0 + row;
        if (node >= NN) continue;
        float4 d = *(float4*)(sD + row * LDF + c4 * 4);
        int col = c4 * 4;
        float4 o;
        o.x = fmaxf(d.x + __ldg(&b2[col + 0]), 0.f);
        o.y = fmaxf(d.y + __ldg(&b2[col + 1]), 0.f);
        o.z = fmaxf(d.z + __ldg(&b2[col + 2]), 0.f);
        o.w = fmaxf(d.w + __ldg(&b2[col + 3]), 0.f);
        uint2 ov;
        __half2* oh = (__half2*)&ov;
        oh[0] = __floats2half2_rn(o.x, o.y);
        oh[1] = __floats2half2_rn(o.z, o.w);
        *(uint2*)(Out + (size_t)node * HD + col) = ov;
    }
}

// ============================================================
// pipelined HD layer: persistent CTAs, warp-specialized
//  warps 0-5  : MMA crew  (W loads, MMA1, relu, MMA2, epilogue)
//  warps 6-11 : gather crew (CSR gather into double-buffered sA)
// named barriers: FULL[b]=1+b, FREE[b]=3+b (count 384), crew=5 (count 192)
// ============================================================
template<bool POOL>
__global__ void __launch_bounds__(NT, 2)
gin_pipe(const __half* __restrict__ Xh,
         const __half* __restrict__ W1, const float* __restrict__ b1,
         const __half* __restrict__ W2, const float* __restrict__ b2,
         __half* __restrict__ Out) {
    extern __shared__ char smc[];
    __half* sA0 = (__half*)smc;                      // 13056 B
    __half* sA1 = (__half*)(smc + 13056);            // 13056 B
    __half* sWh = (__half*)(smc + 26112);            // 34816 B
    float*  sD  = (float*)(smc + 26112);             // alias of sWh

    int tid = threadIdx.x;
    int wid = tid >> 5;

    if (wid < 6) {
        // ---------------- MMA crew (192 threads) ----------------
        int u0 = wid * 2, u1 = wid * 2 + 1;
        int wr0 = u0 % 3, nc0 = u0 / 3;
        int wr1 = u1 % 3, nc1 = u1 / 3;
        wmma::fragment<wmma::accumulator, 16, 16, 16, float> acc[2][2];

        auto loadW = [&](const __half* __restrict__ src) {
            for (int idx = tid; idx < 128 * 16; idx += 192) {
                int row = idx >> 4, c = idx & 15;
                uint4 v = __ldg((const uint4*)src + (size_t)row * 16 + c);
                *(uint4*)(sWh + row * LDH + c * 8) = v;
            }
        };
        auto mmaPhase = [&](const __half* sA) {
#pragma unroll
            for (int j = 0; j < 2; j++)
#pragma unroll
                for (int n = 0; n < 2; n++) wmma::fill_fragment(acc[j][n], 0.f);
            for (int k = 0; k < 8; k++) {
                wmma::fragment<wmma::matrix_a, 16, 16, 16, __half, wmma::row_major> af0, af1;
                wmma::load_matrix_sync(af0, sA + wr0 * 16 * LDH + k * 16, LDH);
                wmma::load_matrix_sync(af1, sA + wr1 * 16 * LDH + k * 16, LDH);
#pragma unroll
                for (int n = 0; n < 2; n++) {
                    wmma::fragment<wmma::matrix_b, 16, 16, 16, __half, wmma::row_major> bf;
                    wmma::load_matrix_sync(bf, sWh + k * 16 * LDH + nc0 * 32 + n * 16, LDH);
                    wmma::mma_sync(acc[0][n], af0, bf, acc[0][n]);
                }
#pragma unroll
                for (int n = 0; n < 2; n++) {
                    wmma::fragment<wmma::matrix_b, 16, 16, 16, __half, wmma::row_major> bf;
                    wmma::load_matrix_sync(bf, sWh + k * 16 * LDH + nc1 * 32 + n * 16, LDH);
                    wmma::mma_sync(acc[1][n], af1, bf, acc[1][n]);
                }
            }
        };
        auto storeAcc = [&]() {
#pragma unroll
            for (int n = 0; n < 2; n++)
                wmma::store_matrix_sync(sD + wr0 * 16 * LDF + nc0 * 32 + n * 16, acc[0][n], LDF, wmma::mem_row_major);
#pragma unroll
            for (int n = 0; n < 2; n++)
                wmma::store_matrix_sync(sD + wr1 * 16 * LDF + nc1 * 32 + n * 16, acc[1][n], LDF, wmma::mem_row_major);
        };

        int k = 0;
        for (int t = blockIdx.x; t < NTILES; t += gridDim.x, k++) {
            int b = k & 1;
            __half* sA = b ? sA1 : sA0;
            int r0 = t * TM;

            loadW(W1);
            NBAR_SYNC(5, 192);           // W1 visible to crew
            NBAR_SYNC(1 + b, 384);       // wait gather FULL

            mmaPhase(sA);                // MMA1
            NBAR_SYNC(5, 192);           // crew done reading W1
            storeAcc();                  // sD (aliases sWh)
            NBAR_SYNC(5, 192);
            for (int idx = tid; idx < TM * 128; idx += 192) {   // relu -> T in sA
                int row = idx >> 7, col = idx & 127;
                float v = fmaxf(sD[row * LDF + col] + __ldg(&b1[col]), 0.f);
                sA[row * LDH + col] = __float2half_rn(v);
            }
            NBAR_SYNC(5, 192);           // relu reads of sD done
            loadW(W2);
            NBAR_SYNC(5, 192);

            mmaPhase(sA);                // MMA2 (reads T)
            NBAR_ARRIVE(3 + b, 384);     // release sA buffer to gather crew
            NBAR_SYNC(5, 192);           // crew done reading W2
            storeAcc();
            NBAR_SYNC(5, 192);

            for (int idx = tid; idx < TM * 32; idx += 192) {    // epilogue
                int row = idx >> 5, c4 = idx & 31;
                int node = r0 + row;
                if (node >= NN) continue;
                float4 d = *(float4*)(sD + row * LDF + c4 * 4);
                uint2 rv = __ldg((const uint2*)(Xh + (size_t)node * HD + c4 * 4));
                const __half2* rh = (const __half2*)&rv;
                float2 r01 = __half22float2(rh[0]);
                float2 r23 = __half22float2(rh[1]);
                int col = c4 * 4;
                float4 o;
                o.x = fmaxf(d.x + __ldg(&b2[col + 0]) + r01.x, 0.f);
                o.y = fmaxf(d.y + __ldg(&b2[col + 1]) + r01.y, 0.f);
                o.z = fmaxf(d.z + __ldg(&b2[col + 2]) + r23.x, 0.f);
                o.w = fmaxf(d.w + __ldg(&b2[col + 3]) + r23.y, 0.f);
                if (POOL) {
                    int bb = __ldg(&g_batch[node]);
                    float* p = g_sums + (size_t)bb * HD + col;
                    asm volatile("red.global.add.v4.f32 [%0], {%1,%2,%3,%4};"
                                 :: "l"(p), "f"(o.x), "f"(o.y), "f"(o.z), "f"(o.w) : "memory");
                } else {
                    uint2 ov;
                    __half2* oh = (__half2*)&ov;
                    oh[0] = __floats2half2_rn(o.x, o.y);
                    oh[1] = __floats2half2_rn(o.z, o.w);
                    *(uint2*)(Out + (size_t)node * HD + col) = ov;
                }
            }
            NBAR_SYNC(5, 192);           // epilogue reads done before next W1 load
        }
    } else {
        // ---------------- gather crew (192 threads) ----------------
        int gtid = tid - 192;
        int hw = gtid >> 4;        // 0..11
        int t4 = gtid & 15;
        const uint4* Xr = (const uint4*)Xh;

        int k = 0;
        for (int t = blockIdx.x; t < NTILES; t += gridDim.x, k++) {
            int b = k & 1;
            __half* sA = b ? sA1 : sA0;
            int r0 = t * TM;
            if (k >= 2) NBAR_SYNC(3 + b, 384);   // wait buffer free
#pragma unroll
            for (int rr = 0; rr < 4; rr++) {
                int row = hw * 4 + rr;
                int node = r0 + row;
                float2 a[4] = {{0.f,0.f},{0.f,0.f},{0.f,0.f},{0.f,0.f}};
                if (node < NN) {
                    uint4 v = __ldg(Xr + (size_t)node * 16 + t4);
                    const __half2* hh = (const __half2*)&v;
#pragma unroll
                    for (int q = 0; q < 4; q++) a[q] = __half22float2(hh[q]);
                    int beg = __ldg(&g_rowstart[node]);
                    int end = __ldg(&g_rowstart[node + 1]);
                    int i = beg;
                    for (; i + 4 <= end; i += 4) {
                        int s0 = __ldg(&g_csr[i + 0]);
                        int s1 = __ldg(&g_csr[i + 1]);
                        int s2 = __ldg(&g_csr[i + 2]);
                        int s3 = __ldg(&g_csr[i + 3]);
                        uint4 v0 = __ldg(Xr + (size_t)s0 * 16 + t4);
                        uint4 v1 = __ldg(Xr + (size_t)s1 * 16 + t4);
                        uint4 v2 = __ldg(Xr + (size_t)s2 * 16 + t4);
                        uint4 v3 = __ldg(Xr + (size_t)s3 * 16 + t4);
                        const __half2* h0 = (const __half2*)&v0;
                        const __half2* h1 = (const __half2*)&v1;
                        const __half2* h2 = (const __half2*)&v2;
                        const __half2* h3 = (const __half2*)&v3;
#pragma unroll
                        for (int q = 0; q < 4; q++) {
                            float2 f0 = __half22float2(h0[q]);
                            float2 f1 = __half22float2(h1[q]);
                            float2 f2 = __half22float2(h2[q]);
                            float2 f3 = __half22float2(h3[q]);
                            a[q].x += (f0.x + f1.x) + (f2.x + f3.x);
                            a[q].y += (f0.y + f1.y) + (f2.y + f3.y);
                        }
                    }
                    for (; i < end; i++) {
                        int s = __ldg(&g_csr[i]);
                        uint4 v2 = __ldg(Xr + (size_t)s * 16 + t4);
                        const __half2* h2 = (const __half2*)&v2;
#pragma unroll
                        for (int q = 0; q < 4; q++) {
                            float2 f = __half22float2(h2[q]);
                            a[q].x += f.x;
                            a[q].y += f.y;
                        }
                    }
                }
                uint4 o;
                __half2* oh = (__half2*)&o;
#pragma unroll
                for (int q = 0; q < 4; q++) oh[q] = __floats2half2_rn(a[q].x, a[q].y);
                *(uint4*)(sA + row * LDH + t4 * 8) = o;
            }
            NBAR_ARRIVE(1 + b, 384);     // buffer full
        }
    }
}

// ============================================================
// fc head (graph count via binary search on sorted batch)
// ============================================================
__global__ void __launch_bounds__(128)
head_kernel(const float* __restrict__ fW1, const float* __restrict__ fb1,
            const float* __restrict__ fW2, const float* __restrict__ fb2,
            float* __restrict__ out) {
    int g = blockIdx.x;
    int t = threadIdx.x;
    __shared__ float sp[HD];
    __shared__ float red[HD];
    __shared__ int s_cnt;
    if (t == 0) {
        int lo = 0, hi = NN;
        while (lo < hi) { int m = (lo + hi) >> 1; if (g_batch[m] < g) lo = m + 1; else hi = m; }
        int lo2 = lo, hi2 = NN;
        while (lo2 < hi2) { int m = (lo2 + hi2) >> 1; if (g_batch[m] < g + 1) lo2 = m + 1; else hi2 = m; }
        s_cnt = lo2 - lo;
    }
    __syncthreads();
    float inv = 1.0f / fmaxf((float)s_cnt, 1.0f);
    sp[t] = g_sums[(size_t)g * HD + t] * inv;
    __syncthreads();
    float acc = 0.f;
#pragma unroll 8
    for (int k = 0; k < HD; k++) acc = fmaf(sp[k], __ldg(&fW1[(size_t)k * HD + t]), acc);
    float hh = acc + __ldg(&fb1[t]);
    hh = (hh > 0.f) ? hh : hh * SLOPE;
    red[t] = hh * __ldg(&fW2[t]);
    __syncthreads();
    for (int s = 64; s > 0; s >>= 1) {
        if (t < s) red[t] += red[t + s];
        __syncthreads();
    }
    if (t == 0) out[g] = red[0] + __ldg(&fb2[0]);
}

// ============================================================
// launch
// ============================================================
extern "C" void kernel_launch(void* const* d_in, const int* in_sizes, int n_in,
                              void* d_out, int out_size) {
    const float* x     = (const float*)d_in[0];
    const void*  ei    = d_in[1];
    const void*  batch = d_in[2];
    const float* l0_W1   = (const float*)d_in[3];
    const float* l0_b1   = (const float*)d_in[4];
    const float* l0_W2   = (const float*)d_in[5];
    const float* l0_b2   = (const float*)d_in[6];
    const float* l0_Wres = (const float*)d_in[7];
    const float* Ws1 = (const float*)d_in[8];
    const float* bs1 = (const float*)d_in[9];
    const float* Ws2 = (const float*)d_in[10];
    const float* bs2 = (const float*)d_in[11];
    const float* fW1 = (const float*)d_in[12];
    const float* fb1 = (const float*)d_in[13];
    const float* fW2 = (const float*)d_in[14];
    const float* fb2 = (const float*)d_in[15];
    float* out = (float*)d_out;

    __half *h0, *h1, *wh;
    cudaGetSymbolAddress((void**)&h0, g_h0);
    cudaGetSymbolAddress((void**)&h1, g_h1);
    cudaGetSymbolAddress((void**)&wh, g_wh);

    const int DSM_L0   = 47872;   // sAh + sWh (sD aliased)
    const int DSM_PIPE = 60928;   // sA0 + sA1 + sWh (sD aliased)
    static bool attr_set = false;
    if (!attr_set) {
        cudaFuncSetAttribute(gin_l0,           cudaFuncAttributeMaxDynamicSharedMemorySize, DSM_L0);
        cudaFuncSetAttribute(gin_pipe<false>,  cudaFuncAttributeMaxDynamicSharedMemorySize, DSM_PIPE);
        cudaFuncSetAttribute(gin_pipe<true>,   cudaFuncAttributeMaxDynamicSharedMemorySize, DSM_PIPE);
        cudaFuncSetAttribute(gin_l0,           cudaFuncAttributePreferredSharedMemoryCarveout, 100);
        cudaFuncSetAttribute(gin_pipe<false>,  cudaFuncAttributePreferredSharedMemoryCarveout, 100);
        cudaFuncSetAttribute(gin_pipe<true>,   cudaFuncAttributePreferredSharedMemoryCarveout, 100);
        attr_set = true;
    }

    // ---- setup ----
    zero_detect<<<(NG * HD + 255) / 256, 256>>>((const int*)ei);
    hist_conv<<<(NE + 255) / 256, 256>>>(ei, batch);
    scan_deg<<<1, 1024>>>();
    fill_csr_convw<<<(NE + 255) / 256, 256>>>(ei, l0_W1, l0_W2, l0_Wres, Ws1, Ws2);

    // ---- layer 0 (R14-style fused kernel) ----
    gin_l0<<<NTILES, NT, DSM_L0>>>(
        x, wh + OW_W10, l0_b1, wh + OW_W20, l0_b2, wh + OW_RES, h0);

    // ---- layers 1..3: persistent pipelined kernel ----
    int dev = 0; cudaGetDevice(&dev);
    int nsm = 148;
    cudaDeviceGetAttribute(&nsm, cudaDevAttrMultiProcessorCount, dev);
    int pgrid = nsm * 2;
    if (pgrid > NTILES) pgrid = NTILES;

    gin_pipe<false><<<pgrid, NT, DSM_PIPE>>>(
        h0, wh + OW_WS1, bs1, wh + OW_WS2, bs2, h1);
    gin_pipe<false><<<pgrid, NT, DSM_PIPE>>>(
        h1, wh + OW_WS1 + 16384, bs1 + HD, wh + OW_WS2 + 16384, bs2 + HD, h0);
    gin_pipe<true><<<pgrid, NT, DSM_PIPE>>>(
        h0, wh + OW_WS1 + 32768, bs1 + 2 * HD, wh + OW_WS2 + 32768, bs2 + 2 * HD, nullptr);

    // ---- head ----
    head_kernel<<<NG, 128>>>(fW1, fb1, fW2, fb2, out);
}

// round 16
// speedup vs baseline: 1.0371x; 1.0371x over previous
#include <cuda_runtime.h>
#include <cuda_fp16.h>
#include <mma.h>
#include <cstdint>

using namespace nvcuda;

// ---------------- problem constants ----------------
constexpr int NN = 50000;
constexpr int NE = 800000;
constexpr int IND = 64;
constexpr int HD = 128;
constexpr int NG = 1024;
constexpr float SLOPE = 0.01f;

constexpr int TM  = 48;    // rows per block tile (3 wmma row-tiles)
constexpr int LDH = 136;   // half smem leading dim
constexpr int LDF = 132;   // float smem leading dim
constexpr int NT  = 384;   // threads per block (12 warps)
constexpr int NTILES = (NN + TM - 1) / TM;   // 1042

// ---------------- scratch (device globals) ----------------
__device__ __align__(256) __half g_h0[(size_t)NN * HD];
__device__ __align__(256) __half g_h1[(size_t)NN * HD];
__device__ __align__(256) __half g_wh[131072];       // all weights, fp16
__device__ __align__(256) float g_sums[(size_t)NG * HD];
__device__ __align__(256) int   g_batch[NN];
__device__ __align__(256) int   g_deg[NN];
__device__ __align__(256) int   g_cur[NN];
__device__ __align__(256) int   g_rowstart[NN + 1];
__device__ __align__(256) int   g_csr[NE];
__device__ int g_is64;

// weight offsets in g_wh (halves)
constexpr int OW_RES = 0;        // [64][128]
constexpr int OW_W10 = 8192;     // [64][128]
constexpr int OW_W20 = 16384;    // [128][128]
constexpr int OW_WS1 = 32768;    // 3 x [128][128]
constexpr int OW_WS2 = 81920;    // 3 x [128][128]

// ============================================================
// setup kernels
// ============================================================
__global__ void zero_detect(const int* __restrict__ rawE) {
    int i = blockIdx.x * blockDim.x + threadIdx.x;
    if (i < NN) { g_deg[i] = 0; g_cur[i] = 0; }
    if (i < NG * HD) g_sums[i] = 0.f;
    if (blockIdx.x == 0) {
        __shared__ int s_any;
        if (threadIdx.x == 0) s_any = 0;
        __syncthreads();
        int bad = 0;
        for (int k = threadIdx.x; k < 4096; k += blockDim.x) bad |= rawE[2 * k + 1];
        if (bad) atomicOr(&s_any, 1);
        __syncthreads();
        if (threadIdx.x == 0) g_is64 = (s_any == 0) ? 1 : 0;
    }
}
__global__ void hist_conv(const void* __restrict__ rawE, const void* __restrict__ rawB) {
    int i = blockIdx.x * blockDim.x + threadIdx.x;
    int is64 = g_is64;
    if (i < NE) {
        int d = is64 ? (int)((const long long*)rawE)[NE + i] : ((const int*)rawE)[NE + i];
        atomicAdd(&g_deg[d], 1);
    }
    if (i < NN) {
        g_batch[i] = is64 ? (int)((const long long*)rawB)[i] : ((const int*)rawB)[i];
    }
}
__global__ void __launch_bounds__(1024) scan_deg() {
    __shared__ int part[1024];
    int tid = threadIdx.x;
    const int CH = (NN + 1023) / 1024;
    int base = tid * CH;
    int s = 0;
    for (int i = 0; i < CH; i++) {
        int idx = base + i;
        if (idx < NN) s += g_deg[idx];
    }
    part[tid] = s;
    __syncthreads();
    for (int off = 1; off < 1024; off <<= 1) {
        int v = (tid >= off) ? part[tid - off] : 0;
        __syncthreads();
        part[tid] += v;
        __syncthreads();
    }
    int run = (tid > 0) ? part[tid - 1] : 0;
    for (int i = 0; i < CH; i++) {
        int idx = base + i;
        if (idx < NN) {
            g_rowstart[idx] = run;
            run += g_deg[idx];
        }
    }
    if (tid == 1023) g_rowstart[NN] = run;
}
// fill CSR + convert weights (independent work fused into one launch)
__global__ void fill_csr_convw(const void* __restrict__ rawE,
                               const float* __restrict__ l0_W1, const float* __restrict__ l0_W2,
                               const float* __restrict__ l0_Wres,
                               const float* __restrict__ Ws1, const float* __restrict__ Ws2) {
    int e = blockIdx.x * blockDim.x + threadIdx.x;
    if (e < 131072) {
        float v;
        if (e < 8192)        v = __ldg(&l0_Wres[e]);
        else if (e < 16384)  v = __ldg(&l0_W1[e - 8192]);
        else if (e < 32768)  v = __ldg(&l0_W2[e - 16384]);
        else if (e < 81920)  v = __ldg(&Ws1[e - 32768]);
        else                 v = __ldg(&Ws2[e - 81920]);
        g_wh[e] = __float2half_rn(v);
    }
    if (e >= NE) return;
    int is64 = g_is64;
    int s = is64 ? (int)((const long long*)rawE)[e]      : ((const int*)rawE)[e];
    int d = is64 ? (int)((const long long*)rawE)[NE + e] : ((const int*)rawE)[NE + e];
    int p = atomicAdd(&g_cur[d], 1);
    g_csr[g_rowstart[d] + p] = s;
}

// ============================================================
// fused GIN layer, 48-row tile, 4 CTAs/SM, persistent grid-stride:
//   A[row] = X[node] + sum_{src in csr[node]} X[src]
//   Out = relu( relu(A@W1 + b1) @ W2 + b2 + Res )
// 12 warps: wrow = wid % 3, ncg = wid / 3. sD aliases sWh.
// ============================================================
template<int K1, bool L0, bool POOL>
__global__ void __launch_bounds__(NT, 4)
gin_fused(const __half* __restrict__ Xh,   // layers 1..3 input
          const float* __restrict__ Xf,    // L0 raw x
          const __half* __restrict__ W1, const float* __restrict__ b1,
          const __half* __restrict__ W2, const float* __restrict__ b2,
          const __half* __restrict__ Wres,
          __half* __restrict__ Out) {
    extern __shared__ char smc[];
    __half* sAh = (__half*)smc;                      // TM x LDH half   (13056 B)
    __half* sWh = (__half*)(smc + 13056);            // 128 x LDH half  (34816 B)
    float*  sD  = (float*)(smc + 13056);             // ALIAS of sWh

    int tid = threadIdx.x;
    int wid = tid >> 5;
    int wrow = wid % 3;
    int ncg  = wid / 3;

    wmma::fragment<wmma::accumulator, 16, 16, 16, float> acc[2];

    auto loadW = [&](const __half* __restrict__ src, int K) {
        int n = K * 16;
        for (int idx = tid; idx < n; idx += NT) {
            int row = idx >> 4, c = idx & 15;
            uint4 v = __ldg((const uint4*)src + (size_t)row * 16 + c);
            *(uint4*)(sWh + row * LDH + c * 8) = v;
        }
    };
    auto mmaAccum = [&](int ksteps) {
        for (int k = 0; k < ksteps; k++) {
            wmma::fragment<wmma::matrix_a, 16, 16, 16, __half, wmma::row_major> af;
            wmma::load_matrix_sync(af, sAh + wrow * 16 * LDH + k * 16, LDH);
#pragma unroll
            for (int n = 0; n < 2; n++) {
                wmma::fragment<wmma::matrix_b, 16, 16, 16, __half, wmma::row_major> bf;
                wmma::load_matrix_sync(bf, sWh + k * 16 * LDH + ncg * 32 + n * 16, LDH);
                wmma::mma_sync(acc[n], af, bf, acc[n]);
            }
        }
    };
    auto mmaPhase = [&](int ksteps) {
#pragma unroll
        for (int n = 0; n < 2; n++) wmma::fill_fragment(acc[n], 0.f);
        mmaAccum(ksteps);
    };
    auto storeAcc = [&]() {
#pragma unroll
        for (int n = 0; n < 2; n++)
            wmma::store_matrix_sync(sD + wrow * 16 * LDF + ncg * 32 + n * 16, acc[n], LDF, wmma::mem_row_major);
    };

    for (int tile = blockIdx.x; tile < NTILES; tile += gridDim.x) {
        int r0 = tile * TM;

        // ---- gather into sAh (2 rows per half-warp) ----
        {
            int hw = tid >> 4;
            int t = tid & 15;
#pragma unroll
            for (int rr = 0; rr < 2; rr++) {
                int row = hw * 2 + rr;
                int node = r0 + row;
                if (L0) {
                    float4 a = make_float4(0.f, 0.f, 0.f, 0.f);
                    if (node < NN) {
                        a = __ldg((const float4*)(Xf + (size_t)node * 64) + t);
                        int beg = __ldg(&g_rowstart[node]);
                        int end = __ldg(&g_rowstart[node + 1]);
                        int i = beg;
                        for (; i + 4 <= end; i += 4) {
                            int s0 = __ldg(&g_csr[i + 0]);
                            int s1 = __ldg(&g_csr[i + 1]);
                            int s2 = __ldg(&g_csr[i + 2]);
                            int s3 = __ldg(&g_csr[i + 3]);
                            float4 v0 = __ldg((const float4*)(Xf + (size_t)s0 * 64) + t);
                            float4 v1 = __ldg((const float4*)(Xf + (size_t)s1 * 64) + t);
                            float4 v2 = __ldg((const float4*)(Xf + (size_t)s2 * 64) + t);
                            float4 v3 = __ldg((const float4*)(Xf + (size_t)s3 * 64) + t);
                            a.x += (v0.x + v1.x) + (v2.x + v3.x);
                            a.y += (v0.y + v1.y) + (v2.y + v3.y);
                            a.z += (v0.z + v1.z) + (v2.z + v3.z);
                            a.w += (v0.w + v1.w) + (v2.w + v3.w);
                        }
                        for (; i < end; i++) {
                            int s = __ldg(&g_csr[i]);
                            float4 v = __ldg((const float4*)(Xf + (size_t)s * 64) + t);
                            a.x += v.x; a.y += v.y; a.z += v.z; a.w += v.w;
                        }
                    }
                    __half2* o = (__half2*)(sAh + row * LDH + t * 4);
                    o[0] = __floats2half2_rn(a.x, a.y);
                    o[1] = __floats2half2_rn(a.z, a.w);
                } else {
                    const uint4* Xr = (const uint4*)Xh;
                    float2 a[4] = {{0.f,0.f},{0.f,0.f},{0.f,0.f},{0.f,0.f}};
                    if (node < NN) {
                        uint4 v = __ldg(Xr + (size_t)node * 16 + t);
                        const __half2* hh = (const __half2*)&v;
#pragma unroll
                        for (int q = 0; q < 4; q++) a[q] = __half22float2(hh[q]);
                        int beg = __ldg(&g_rowstart[node]);
                        int end = __ldg(&g_rowstart[node + 1]);
                        int i = beg;
                        for (; i + 4 <= end; i += 4) {
                            int s0 = __ldg(&g_csr[i + 0]);
                            int s1 = __ldg(&g_csr[i + 1]);
                            int s2 = __ldg(&g_csr[i + 2]);
                            int s3 = __ldg(&g_csr[i + 3]);
                            uint4 v0 = __ldg(Xr + (size_t)s0 * 16 + t);
                            uint4 v1 = __ldg(Xr + (size_t)s1 * 16 + t);
                            uint4 v2 = __ldg(Xr + (size_t)s2 * 16 + t);
                            uint4 v3 = __ldg(Xr + (size_t)s3 * 16 + t);
                            const __half2* h0 = (const __half2*)&v0;
                            const __half2* h1 = (const __half2*)&v1;
                            const __half2* h2 = (const __half2*)&v2;
                            const __half2* h3 = (const __half2*)&v3;
#pragma unroll
                            for (int q = 0; q < 4; q++) {
                                float2 f0 = __half22float2(h0[q]);
                                float2 f1 = __half22float2(h1[q]);
                                float2 f2 = __half22float2(h2[q]);
                                float2 f3 = __half22float2(h3[q]);
                                a[q].x += (f0.x + f1.x) + (f2.x + f3.x);
                                a[q].y += (f0.y + f1.y) + (f2.y + f3.y);
                            }
                        }
                        for (; i < end; i++) {
                            int s = __ldg(&g_csr[i]);
                            uint4 v2 = __ldg(Xr + (size_t)s * 16 + t);
                            const __half2* h2 = (const __half2*)&v2;
#pragma unroll
                            for (int q = 0; q < 4; q++) {
                                float2 f = __half22float2(h2[q]);
                                a[q].x += f.x;
                                a[q].y += f.y;
                            }
                        }
                    }
                    uint4 o;
                    __half2* oh = (__half2*)&o;
#pragma unroll
                    for (int q = 0; q < 4; q++) oh[q] = __floats2half2_rn(a[q].x, a[q].y);
                    *(uint4*)(sAh + row * LDH + t * 8) = o;
                }
            }
        }
        loadW(W1, K1);
        __syncthreads();

        // ---- phase 1: T = relu(A @ W1 + b1) ----
        mmaPhase(K1 / 16);
        __syncthreads();            // all warps done reading sWh (W1)
        storeAcc();                 // write sD (aliases sWh)
        __syncthreads();
        for (int idx = tid; idx < TM * 128; idx += NT) {
            int row = idx >> 7, col = idx & 127;
            float v = fmaxf(sD[row * LDF + col] + __ldg(&b1[col]), 0.f);
            sAh[row * LDH + col] = __float2half_rn(v);
        }
        __syncthreads();            // relu reads of sD done
        loadW(W2, 128);             // overwrite aliased region with W2
        __syncthreads();

        // ---- phase 2: D = T @ W2 (acc stays in regs) ----
        mmaPhase(8);

        // ---- L0: acc += x @ Wres (register-resident residual) ----
        if (L0) {
            __syncthreads();        // all warps done reading sAh / sWh
            for (int idx = tid; idx < TM * 16; idx += NT) {
                int row = idx >> 4, c4 = idx & 15;
                float4 v = make_float4(0.f, 0.f, 0.f, 0.f);
                if (r0 + row < NN) v = __ldg((const float4*)(Xf + (size_t)(r0 + row) * 64) + c4);
                __half2* o = (__half2*)(sAh + row * LDH + c4 * 4);
                o[0] = __floats2half2_rn(v.x, v.y);
                o[1] = __floats2half2_rn(v.z, v.w);
            }
            loadW(Wres, 64);
            __syncthreads();
            mmaAccum(4);
        }
        __syncthreads();            // all warps done reading sWh
        storeAcc();                 // write sD (aliases sWh)
        __syncthreads();

        // ---- epilogue: o = relu(D + b2 + Res) ----
        for (int idx = tid; idx < TM * 32; idx += NT) {
            int row = idx >> 5, c4 = idx & 31;
            int node = r0 + row;
            if (node >= NN) continue;
            float4 d = *(float4*)(sD + row * LDF + c4 * 4);
            float4 res4 = make_float4(0.f, 0.f, 0.f, 0.f);
            if (!L0) {
                uint2 rv = __ldg((const uint2*)(Xh + (size_t)node * HD + c4 * 4));
                const __half2* rh = (const __half2*)&rv;
                float2 r01 = __half22float2(rh[0]);
                float2 r23 = __half22float2(rh[1]);
                res4 = make_float4(r01.x, r01.y, r23.x, r23.y);
            }
            int col = c4 * 4;
            float4 o;
            o.x = fmaxf(d.x + __ldg(&b2[col + 0]) + res4.x, 0.f);
            o.y = fmaxf(d.y + __ldg(&b2[col + 1]) + res4.y, 0.f);
            o.z = fmaxf(d.z + __ldg(&b2[col + 2]) + res4.z, 0.f);
            o.w = fmaxf(d.w + __ldg(&b2[col + 3]) + res4.w, 0.f);
            if (POOL) {
                int b = __ldg(&g_batch[node]);
                float* p = g_sums + (size_t)b * HD + col;
                asm volatile("red.global.add.v4.f32 [%0], {%1,%2,%3,%4};"
                             :: "l"(p), "f"(o.x), "f"(o.y), "f"(o.z), "f"(o.w) : "memory");
            } else {
                uint2 ov;
                __half2* oh = (__half2*)&ov;
                oh[0] = __floats2half2_rn(o.x, o.y);
                oh[1] = __floats2half2_rn(o.z, o.w);
                *(uint2*)(Out + (size_t)node * HD + col) = ov;
            }
        }
        __syncthreads();            // epilogue reads of sD done before next loadW(W1)
    }
}

// ============================================================
// fc head (graph count via binary search on sorted batch)
// ============================================================
__global__ void __launch_bounds__(128)
head_kernel(const float* __restrict__ fW1, const float* __restrict__ fb1,
            const float* __restrict__ fW2, const float* __restrict__ fb2,
            float* __restrict__ out) {
    int g = blockIdx.x;
    int t = threadIdx.x;
    __shared__ float sp[HD];
    __shared__ float red[HD];
    __shared__ int s_cnt;
    if (t == 0) {
        int lo = 0, hi = NN;
        while (lo < hi) { int m = (lo + hi) >> 1; if (g_batch[m] < g) lo = m + 1; else hi = m; }
        int lo2 = lo, hi2 = NN;
        while (lo2 < hi2) { int m = (lo2 + hi2) >> 1; if (g_batch[m] < g + 1) lo2 = m + 1; else hi2 = m; }
        s_cnt = lo2 - lo;
    }
    __syncthreads();
    float inv = 1.0f / fmaxf((float)s_cnt, 1.0f);
    sp[t] = g_sums[(size_t)g * HD + t] * inv;
    __syncthreads();
    float acc = 0.f;
#pragma unroll 8
    for (int k = 0; k < HD; k++) acc = fmaf(sp[k], __ldg(&fW1[(size_t)k * HD + t]), acc);
    float hh = acc + __ldg(&fb1[t]);
    hh = (hh > 0.f) ? hh : hh * SLOPE;
    red[t] = hh * __ldg(&fW2[t]);
    __syncthreads();
    for (int s = 64; s > 0; s >>= 1) {
        if (t < s) red[t] += red[t + s];
        __syncthreads();
    }
    if (t == 0) out[g] = red[0] + __ldg(&fb2[0]);
}

// ============================================================
// launch
// ============================================================
extern "C" void kernel_launch(void* const* d_in, const int* in_sizes, int n_in,
                              void* d_out, int out_size) {
    const float* x     = (const float*)d_in[0];
    const void*  ei    = d_in[1];
    const void*  batch = d_in[2];
    const float* l0_W1   = (const float*)d_in[3];
    const float* l0_b1   = (const float*)d_in[4];
    const float* l0_W2   = (const float*)d_in[5];
    const float* l0_b2   = (const float*)d_in[6];
    const float* l0_Wres = (const float*)d_in[7];
    const float* Ws1 = (const float*)d_in[8];
    const float* bs1 = (const float*)d_in[9];
    const float* Ws2 = (const float*)d_in[10];
    const float* bs2 = (const float*)d_in[11];
    const float* fW1 = (const float*)d_in[12];
    const float* fb1 = (const float*)d_in[13];
    const float* fW2 = (const float*)d_in[14];
    const float* fb2 = (const float*)d_in[15];
    float* out = (float*)d_out;

    __half *h0, *h1, *wh;
    cudaGetSymbolAddress((void**)&h0, g_h0);
    cudaGetSymbolAddress((void**)&h1, g_h1);
    cudaGetSymbolAddress((void**)&wh, g_wh);

    const int DSM = 47872;   // sAh(13056) + sWh(34816); sD aliases sWh
    static bool attr_set = false;
    if (!attr_set) {
        cudaFuncSetAttribute(gin_fused<64, true, false>,   cudaFuncAttributeMaxDynamicSharedMemorySize, DSM);
        cudaFuncSetAttribute(gin_fused<128, false, false>, cudaFuncAttributeMaxDynamicSharedMemorySize, DSM);
        cudaFuncSetAttribute(gin_fused<128, false, true>,  cudaFuncAttributeMaxDynamicSharedMemorySize, DSM);
        cudaFuncSetAttribute(gin_fused<64, true, false>,   cudaFuncAttributePreferredSharedMemoryCarveout, 100);
        cudaFuncSetAttribute(gin_fused<128, false, false>, cudaFuncAttributePreferredSharedMemoryCarveout, 100);
        cudaFuncSetAttribute(gin_fused<128, false, true>,  cudaFuncAttributePreferredSharedMemoryCarveout, 100);
        attr_set = true;
    }

    // ---- setup ----
    zero_detect<<<(NG * HD + 255) / 256, 256>>>((const int*)ei);
    hist_conv<<<(NE + 255) / 256, 256>>>(ei, batch);
    scan_deg<<<1, 1024>>>();
    fill_csr_convw<<<(NE + 255) / 256, 256>>>(ei, l0_W1, l0_W2, l0_Wres, Ws1, Ws2);

    // persistent grid: exactly one wave (4 CTAs/SM)
    int dev = 0; cudaGetDevice(&dev);
    int nsm = 148;
    cudaDeviceGetAttribute(&nsm, cudaDevAttrMultiProcessorCount, dev);
    int pgrid = nsm * 4;
    if (pgrid > NTILES) pgrid = NTILES;

    // ---- 4 fused GIN layers ----
    gin_fused<64, true, false><<<pgrid, NT, DSM>>>(
        nullptr, x, wh + OW_W10, l0_b1, wh + OW_W20, l0_b2, wh + OW_RES, h0);
    gin_fused<128, false, false><<<pgrid, NT, DSM>>>(
        h0, nullptr, wh + OW_WS1, bs1, wh + OW_WS2, bs2, nullptr, h1);
    gin_fused<128, false, false><<<pgrid, NT, DSM>>>(
        h1, nullptr, wh + OW_WS1 + 16384, bs1 + HD, wh + OW_WS2 + 16384, bs2 + HD, nullptr, h0);
    gin_fused<128, false, true><<<pgrid, NT, DSM>>>(
        h0, nullptr, wh + OW_WS1 + 32768, bs1 + 2 * HD, wh + OW_WS2 + 32768, bs2 + 2 * HD, nullptr, nullptr);

    // ---- head ----
    head_kernel<<<NG, 128>>>(fW1, fb1, fW2, fb2, out);
}

// round 17
// speedup vs baseline: 1.1404x; 1.0995x over previous
#include <cuda_runtime.h>
#include <cuda_fp16.h>
#include <cuda_pipeline.h>
#include <mma.h>
#include <cstdint>

using namespace nvcuda;

// ---------------- problem constants ----------------
constexpr int NN = 50000;
constexpr int NE = 800000;
constexpr int IND = 64;
constexpr int HD = 128;
constexpr int NG = 1024;
constexpr float SLOPE = 0.01f;

constexpr int TM  = 48;    // rows per block tile (3 wmma row-tiles)
constexpr int LDH = 136;   // half smem leading dim
constexpr int LDF = 132;   // float smem leading dim
constexpr int NT  = 384;   // threads per block (12 warps)

// ---------------- scratch (device globals) ----------------
__device__ __align__(256) __half g_h0[(size_t)NN * HD];
__device__ __align__(256) __half g_h1[(size_t)NN * HD];
__device__ __align__(256) __half g_wh[131072];       // all weights, fp16
__device__ __align__(256) float g_sums[(size_t)NG * HD];
__device__ __align__(256) int   g_batch[NN];
__device__ __align__(256) int   g_deg[NN];
__device__ __align__(256) int   g_cur[NN];
__device__ __align__(256) int   g_rowstart[NN + 1];
__device__ __align__(256) int   g_csr[NE];
__device__ int g_is64;

// weight offsets in g_wh (halves)
constexpr int OW_RES = 0;        // [64][128]
constexpr int OW_W10 = 8192;     // [64][128]
constexpr int OW_W20 = 16384;    // [128][128]
constexpr int OW_WS1 = 32768;    // 3 x [128][128]
constexpr int OW_WS2 = 81920;    // 3 x [128][128]

// ============================================================
// setup kernels
// ============================================================
__global__ void zero_detect(const int* __restrict__ rawE) {
    int i = blockIdx.x * blockDim.x + threadIdx.x;
    if (i < NN) { g_deg[i] = 0; g_cur[i] = 0; }
    if (i < NG * HD) g_sums[i] = 0.f;
    if (blockIdx.x == 0) {
        __shared__ int s_any;
        if (threadIdx.x == 0) s_any = 0;
        __syncthreads();
        int bad = 0;
        for (int k = threadIdx.x; k < 4096; k += blockDim.x) bad |= rawE[2 * k + 1];
        if (bad) atomicOr(&s_any, 1);
        __syncthreads();
        if (threadIdx.x == 0) g_is64 = (s_any == 0) ? 1 : 0;
    }
}
__global__ void hist_conv(const void* __restrict__ rawE, const void* __restrict__ rawB) {
    int i = blockIdx.x * blockDim.x + threadIdx.x;
    int is64 = g_is64;
    if (i < NE) {
        int d = is64 ? (int)((const long long*)rawE)[NE + i] : ((const int*)rawE)[NE + i];
        atomicAdd(&g_deg[d], 1);
    }
    if (i < NN) {
        g_batch[i] = is64 ? (int)((const long long*)rawB)[i] : ((const int*)rawB)[i];
    }
}
__global__ void __launch_bounds__(1024) scan_deg() {
    __shared__ int part[1024];
    int tid = threadIdx.x;
    const int CH = (NN + 1023) / 1024;
    int base = tid * CH;
    int s = 0;
    for (int i = 0; i < CH; i++) {
        int idx = base + i;
        if (idx < NN) s += g_deg[idx];
    }
    part[tid] = s;
    __syncthreads();
    for (int off = 1; off < 1024; off <<= 1) {
        int v = (tid >= off) ? part[tid - off] : 0;
        __syncthreads();
        part[tid] += v;
        __syncthreads();
    }
    int run = (tid > 0) ? part[tid - 1] : 0;
    for (int i = 0; i < CH; i++) {
        int idx = base + i;
        if (idx < NN) {
            g_rowstart[idx] = run;
            run += g_deg[idx];
        }
    }
    if (tid == 1023) g_rowstart[NN] = run;
}
// fill CSR + convert weights (independent work fused into one launch)
__global__ void fill_csr_convw(const void* __restrict__ rawE,
                               const float* __restrict__ l0_W1, const float* __restrict__ l0_W2,
                               const float* __restrict__ l0_Wres,
                               const float* __restrict__ Ws1, const float* __restrict__ Ws2) {
    int e = blockIdx.x * blockDim.x + threadIdx.x;
    if (e < 131072) {
        float v;
        if (e < 8192)        v = __ldg(&l0_Wres[e]);
        else if (e < 16384)  v = __ldg(&l0_W1[e - 8192]);
        else if (e < 32768)  v = __ldg(&l0_W2[e - 16384]);
        else if (e < 81920)  v = __ldg(&Ws1[e - 32768]);
        else                 v = __ldg(&Ws2[e - 81920]);
        g_wh[e] = __float2half_rn(v);
    }
    if (e >= NE) return;
    int is64 = g_is64;
    int s = is64 ? (int)((const long long*)rawE)[e]      : ((const int*)rawE)[e];
    int d = is64 ? (int)((const long long*)rawE)[NE + e] : ((const int*)rawE)[NE + e];
    int p = atomicAdd(&g_cur[d], 1);
    g_csr[g_rowstart[d] + p] = s;
}

// ============================================================
// fused GIN layer, 48-row tile, 4 CTAs/SM (R14 structure):
//   A[row] = X[node] + sum_{src in csr[node]} X[src]
//   Out = relu( relu(A@W1 + b1) @ W2 + b2 + Res )
// W1 tile prefetched via cp.async BEFORE the gather so its latency
// overlaps the serial neighbor loop. sD aliases sWh.
// ============================================================
template<int K1, bool L0, bool POOL>
__global__ void __launch_bounds__(NT, 4)
gin_fused(const __half* __restrict__ Xh,   // layers 1..3 input
          const float* __restrict__ Xf,    // L0 raw x
          const __half* __restrict__ W1, const float* __restrict__ b1,
          const __half* __restrict__ W2, const float* __restrict__ b2,
          const __half* __restrict__ Wres,
          __half* __restrict__ Out) {
    extern __shared__ char smc[];
    __half* sAh = (__half*)smc;                      // TM x LDH half   (13056 B)
    __half* sWh = (__half*)(smc + 13056);            // 128 x LDH half  (34816 B)
    float*  sD  = (float*)(smc + 13056);             // ALIAS of sWh

    int tid = threadIdx.x;
    int wid = tid >> 5;
    int r0 = blockIdx.x * TM;
    int wrow = wid % 3;            // row-tile 0..2
    int ncg  = wid / 3;            // col-group 0..3 (32 cols each)

    wmma::fragment<wmma::accumulator, 16, 16, 16, float> acc[2];

    // async weight prefetch (LDGSTS): 16B chunks, no staging registers
    auto loadW_async = [&](const __half* __restrict__ src, int K) {
        int n = K * 16;
        for (int idx = tid; idx < n; idx += NT) {
            int row = idx >> 4, c = idx & 15;
            __pipeline_memcpy_async(sWh + row * LDH + c * 8,
                                    (const uint4*)src + (size_t)row * 16 + c, 16);
        }
        __pipeline_commit();
    };
    auto loadW = [&](const __half* __restrict__ src, int K) {
        int n = K * 16;
        for (int idx = tid; idx < n; idx += NT) {
            int row = idx >> 4, c = idx & 15;
            uint4 v = __ldg((const uint4*)src + (size_t)row * 16 + c);
            *(uint4*)(sWh + row * LDH + c * 8) = v;
        }
    };
    auto mmaAccum = [&](int ksteps) {
        for (int k = 0; k < ksteps; k++) {
            wmma::fragment<wmma::matrix_a, 16, 16, 16, __half, wmma::row_major> af;
            wmma::load_matrix_sync(af, sAh + wrow * 16 * LDH + k * 16, LDH);
#pragma unroll
            for (int n = 0; n < 2; n++) {
                wmma::fragment<wmma::matrix_b, 16, 16, 16, __half, wmma::row_major> bf;
                wmma::load_matrix_sync(bf, sWh + k * 16 * LDH + ncg * 32 + n * 16, LDH);
                wmma::mma_sync(acc[n], af, bf, acc[n]);
            }
        }
    };
    auto mmaPhase = [&](int ksteps) {
#pragma unroll
        for (int n = 0; n < 2; n++) wmma::fill_fragment(acc[n], 0.f);
        mmaAccum(ksteps);
    };
    auto storeAcc = [&]() {
#pragma unroll
        for (int n = 0; n < 2; n++)
            wmma::store_matrix_sync(sD + wrow * 16 * LDF + ncg * 32 + n * 16, acc[n], LDF, wmma::mem_row_major);
    };

    // ---- kick off W1 prefetch, then gather (overlapped) ----
    loadW_async(W1, K1);

    // ---- gather into sAh (2 rows per half-warp) ----
    {
        int hw = tid >> 4;
        int t = tid & 15;
#pragma unroll
        for (int rr = 0; rr < 2; rr++) {
            int row = hw * 2 + rr;
            int node = r0 + row;
            if (L0) {
                float4 a = make_float4(0.f, 0.f, 0.f, 0.f);
                if (node < NN) {
                    a = __ldg((const float4*)(Xf + (size_t)node * 64) + t);
                    int beg = __ldg(&g_rowstart[node]);
                    int end = __ldg(&g_rowstart[node + 1]);
                    int i = beg;
                    for (; i + 4 <= end; i += 4) {
                        int s0 = __ldg(&g_csr[i + 0]);
                        int s1 = __ldg(&g_csr[i + 1]);
                        int s2 = __ldg(&g_csr[i + 2]);
                        int s3 = __ldg(&g_csr[i + 3]);
                        float4 v0 = __ldg((const float4*)(Xf + (size_t)s0 * 64) + t);
                        float4 v1 = __ldg((const float4*)(Xf + (size_t)s1 * 64) + t);
                        float4 v2 = __ldg((const float4*)(Xf + (size_t)s2 * 64) + t);
                        float4 v3 = __ldg((const float4*)(Xf + (size_t)s3 * 64) + t);
                        a.x += (v0.x + v1.x) + (v2.x + v3.x);
                        a.y += (v0.y + v1.y) + (v2.y + v3.y);
                        a.z += (v0.z + v1.z) + (v2.z + v3.z);
                        a.w += (v0.w + v1.w) + (v2.w + v3.w);
                    }
                    for (; i < end; i++) {
                        int s = __ldg(&g_csr[i]);
                        float4 v = __ldg((const float4*)(Xf + (size_t)s * 64) + t);
                        a.x += v.x; a.y += v.y; a.z += v.z; a.w += v.w;
                    }
                }
                __half2* o = (__half2*)(sAh + row * LDH + t * 4);
                o[0] = __floats2half2_rn(a.x, a.y);
                o[1] = __floats2half2_rn(a.z, a.w);
            } else {
                const uint4* Xr = (const uint4*)Xh;
                float2 a[4] = {{0.f,0.f},{0.f,0.f},{0.f,0.f},{0.f,0.f}};
                if (node < NN) {
                    uint4 v = __ldg(Xr + (size_t)node * 16 + t);
                    const __half2* hh = (const __half2*)&v;
#pragma unroll
                    for (int q = 0; q < 4; q++) a[q] = __half22float2(hh[q]);
                    int beg = __ldg(&g_rowstart[node]);
                    int end = __ldg(&g_rowstart[node + 1]);
                    int i = beg;
                    for (; i + 4 <= end; i += 4) {
                        int s0 = __ldg(&g_csr[i + 0]);
                        int s1 = __ldg(&g_csr[i + 1]);
                        int s2 = __ldg(&g_csr[i + 2]);
                        int s3 = __ldg(&g_csr[i + 3]);
                        uint4 v0 = __ldg(Xr + (size_t)s0 * 16 + t);
                        uint4 v1 = __ldg(Xr + (size_t)s1 * 16 + t);
                        uint4 v2 = __ldg(Xr + (size_t)s2 * 16 + t);
                        uint4 v3 = __ldg(Xr + (size_t)s3 * 16 + t);
                        const __half2* h0 = (const __half2*)&v0;
                        const __half2* h1 = (const __half2*)&v1;
                        const __half2* h2 = (const __half2*)&v2;
                        const __half2* h3 = (const __half2*)&v3;
#pragma unroll
                        for (int q = 0; q < 4; q++) {
                            float2 f0 = __half22float2(h0[q]);
                            float2 f1 = __half22float2(h1[q]);
                            float2 f2 = __half22float2(h2[q]);
                            float2 f3 = __half22float2(h3[q]);
                            a[q].x += (f0.x + f1.x) + (f2.x + f3.x);
                            a[q].y += (f0.y + f1.y) + (f2.y + f3.y);
                        }
                    }
                    for (; i < end; i++) {
                        int s = __ldg(&g_csr[i]);
                        uint4 v2 = __ldg(Xr + (size_t)s * 16 + t);
                        const __half2* h2 = (const __half2*)&v2;
#pragma unroll
                        for (int q = 0; q < 4; q++) {
                            float2 f = __half22float2(h2[q]);
                            a[q].x += f.x;
                            a[q].y += f.y;
                        }
                    }
                }
                uint4 o;
                __half2* oh = (__half2*)&o;
#pragma unroll
                for (int q = 0; q < 4; q++) oh[q] = __floats2half2_rn(a[q].x, a[q].y);
                *(uint4*)(sAh + row * LDH + t * 8) = o;
            }
        }
    }
    __pipeline_wait_prior(0);   // W1 landed
    __syncthreads();

    // ---- phase 1: T = relu(A @ W1 + b1) ----
    mmaPhase(K1 / 16);
    __syncthreads();            // all warps done reading sWh (W1)
    storeAcc();                 // write sD (aliases sWh)
    __syncthreads();
    for (int idx = tid; idx < TM * 128; idx += NT) {
        int row = idx >> 7, col = idx & 127;
        float v = fmaxf(sD[row * LDF + col] + __ldg(&b1[col]), 0.f);
        sAh[row * LDH + col] = __float2half_rn(v);
    }
    __syncthreads();            // relu reads of sD done
    loadW(W2, 128);             // overwrite aliased region with W2
    __syncthreads();

    // ---- phase 2: D = T @ W2 (acc stays in regs) ----
    mmaPhase(8);

    // ---- L0: acc += x @ Wres (register-resident residual) ----
    if (L0) {
        __syncthreads();        // all warps done reading sAh / sWh
        for (int idx = tid; idx < TM * 16; idx += NT) {
            int row = idx >> 4, c4 = idx & 15;
            float4 v = make_float4(0.f, 0.f, 0.f, 0.f);
            if (r0 + row < NN) v = __ldg((const float4*)(Xf + (size_t)(r0 + row) * 64) + c4);
            __half2* o = (__half2*)(sAh + row * LDH + c4 * 4);
            o[0] = __floats2half2_rn(v.x, v.y);
            o[1] = __floats2half2_rn(v.z, v.w);
        }
        loadW(Wres, 64);
        __syncthreads();
        mmaAccum(4);
    }
    __syncthreads();            // all warps done reading sWh
    storeAcc();                 // write sD (aliases sWh)
    __syncthreads();

    // ---- epilogue: o = relu(D + b2 + Res) ----
    for (int idx = tid; idx < TM * 32; idx += NT) {
        int row = idx >> 5, c4 = idx & 31;
        int node = r0 + row;
        if (node >= NN) continue;
        float4 d = *(float4*)(sD + row * LDF + c4 * 4);
        float4 res4 = make_float4(0.f, 0.f, 0.f, 0.f);
        if (!L0) {
            uint2 rv = __ldg((const uint2*)(Xh + (size_t)node * HD + c4 * 4));
            const __half2* rh = (const __half2*)&rv;
            float2 r01 = __half22float2(rh[0]);
            float2 r23 = __half22float2(rh[1]);
            res4 = make_float4(r01.x, r01.y, r23.x, r23.y);
        }
        int col = c4 * 4;
        float4 o;
        o.x = fmaxf(d.x + __ldg(&b2[col + 0]) + res4.x, 0.f);
        o.y = fmaxf(d.y + __ldg(&b2[col + 1]) + res4.y, 0.f);
        o.z = fmaxf(d.z + __ldg(&b2[col + 2]) + res4.z, 0.f);
        o.w = fmaxf(d.w + __ldg(&b2[col + 3]) + res4.w, 0.f);
        if (POOL) {
            int b = __ldg(&g_batch[node]);
            float* p = g_sums + (size_t)b * HD + col;
            asm volatile("red.global.add.v4.f32 [%0], {%1,%2,%3,%4};"
                         :: "l"(p), "f"(o.x), "f"(o.y), "f"(o.z), "f"(o.w) : "memory");
        } else {
            uint2 ov;
            __half2* oh = (__half2*)&ov;
            oh[0] = __floats2half2_rn(o.x, o.y);
            oh[1] = __floats2half2_rn(o.z, o.w);
            *(uint2*)(Out + (size_t)node * HD + col) = ov;
        }
    }
}

// ============================================================
// fc head (graph count via binary search on sorted batch)
// ============================================================
__global__ void __launch_bounds__(128)
head_kernel(const float* __restrict__ fW1, const float* __restrict__ fb1,
            const float* __restrict__ fW2, const float* __restrict__ fb2,
            float* __restrict__ out) {
    int g = blockIdx.x;
    int t = threadIdx.x;
    __shared__ float sp[HD];
    __shared__ float red[HD];
    __shared__ int s_cnt;
    if (t == 0) {
        int lo = 0, hi = NN;
        while (lo < hi) { int m = (lo + hi) >> 1; if (g_batch[m] < g) lo = m + 1; else hi = m; }
        int lo2 = lo, hi2 = NN;
        while (lo2 < hi2) { int m = (lo2 + hi2) >> 1; if (g_batch[m] < g + 1) lo2 = m + 1; else hi2 = m; }
        s_cnt = lo2 - lo;
    }
    __syncthreads();
    float inv = 1.0f / fmaxf((float)s_cnt, 1.0f);
    sp[t] = g_sums[(size_t)g * HD + t] * inv;
    __syncthreads();
    float acc = 0.f;
#pragma unroll 8
    for (int k = 0; k < HD; k++) acc = fmaf(sp[k], __ldg(&fW1[(size_t)k * HD + t]), acc);
    float hh = acc + __ldg(&fb1[t]);
    hh = (hh > 0.f) ? hh : hh * SLOPE;
    red[t] = hh * __ldg(&fW2[t]);
    __syncthreads();
    for (int s = 64; s > 0; s >>= 1) {
        if (t < s) red[t] += red[t + s];
        __syncthreads();
    }
    if (t == 0) out[g] = red[0] + __ldg(&fb2[0]);
}

// ============================================================
// launch
// ============================================================
extern "C" void kernel_launch(void* const* d_in, const int* in_sizes, int n_in,
                              void* d_out, int out_size) {
    const float* x     = (const float*)d_in[0];
    const void*  ei    = d_in[1];
    const void*  batch = d_in[2];
    const float* l0_W1   = (const float*)d_in[3];
    const float* l0_b1   = (const float*)d_in[4];
    const float* l0_W2   = (const float*)d_in[5];
    const float* l0_b2   = (const float*)d_in[6];
    const float* l0_Wres = (const float*)d_in[7];
    const float* Ws1 = (const float*)d_in[8];
    const float* bs1 = (const float*)d_in[9];
    const float* Ws2 = (const float*)d_in[10];
    const float* bs2 = (const float*)d_in[11];
    const float* fW1 = (const float*)d_in[12];
    const float* fb1 = (const float*)d_in[13];
    const float* fW2 = (const float*)d_in[14];
    const float* fb2 = (const float*)d_in[15];
    float* out = (float*)d_out;

    __half *h0, *h1, *wh;
    cudaGetSymbolAddress((void**)&h0, g_h0);
    cudaGetSymbolAddress((void**)&h1, g_h1);
    cudaGetSymbolAddress((void**)&wh, g_wh);

    const int DSM = 47872;   // sAh(13056) + sWh(34816); sD aliases sWh
    static bool attr_set = false;
    if (!attr_set) {
        cudaFuncSetAttribute(gin_fused<64, true, false>,   cudaFuncAttributeMaxDynamicSharedMemorySize, DSM);
        cudaFuncSetAttribute(gin_fused<128, false, false>, cudaFuncAttributeMaxDynamicSharedMemorySize, DSM);
        cudaFuncSetAttribute(gin_fused<128, false, true>,  cudaFuncAttributeMaxDynamicSharedMemorySize, DSM);
        cudaFuncSetAttribute(gin_fused<64, true, false>,   cudaFuncAttributePreferredSharedMemoryCarveout, 100);
        cudaFuncSetAttribute(gin_fused<128, false, false>, cudaFuncAttributePreferredSharedMemoryCarveout, 100);
        cudaFuncSetAttribute(gin_fused<128, false, true>,  cudaFuncAttributePreferredSharedMemoryCarveout, 100);
        attr_set = true;
    }

    // ---- setup ----
    zero_detect<<<(NG * HD + 255) / 256, 256>>>((const int*)ei);
    hist_conv<<<(NE + 255) / 256, 256>>>(ei, batch);
    scan_deg<<<1, 1024>>>();
    fill_csr_convw<<<(NE + 255) / 256, 256>>>(ei, l0_W1, l0_W2, l0_Wres, Ws1, Ws2);

    const int blocks = (NN + TM - 1) / TM;   // 1042 — HW scheduler balances wave 2

    // ---- 4 fused GIN layers ----
    gin_fused<64, true, false><<<blocks, NT, DSM>>>(
        nullptr, x, wh + OW_W10, l0_b1, wh + OW_W20, l0_b2, wh + OW_RES, h0);
    gin_fused<128, false, false><<<blocks, NT, DSM>>>(
        h0, nullptr, wh + OW_WS1, bs1, wh + OW_WS2, bs2, nullptr, h1);
    gin_fused<128, false, false><<<blocks, NT, DSM>>>(
        h1, nullptr, wh + OW_WS1 + 16384, bs1 + HD, wh + OW_WS2 + 16384, bs2 + HD, nullptr, h0);
    gin_fused<128, false, true><<<blocks, NT, DSM>>>(
        h0, nullptr, wh + OW_WS1 + 32768, bs1 + 2 * HD, wh + OW_WS2 + 32768, bs2 + 2 * HD, nullptr, nullptr);

    // ---- head ----
    head_kernel<<<NG, 128>>>(fW1, fb1, fW2, fb2, out);
}